// round 12
// baseline (speedup 1.0000x reference)
#include <cuda_runtime.h>
#include <cstdint>

#define Bn 4
#define Cn 64
#define Nn 16384
#define On 128
#define Kn 16
#define EPSf 1e-5f
#define NEGf 0.2f
#define FLT_NEG (-3.402823466e38f)
#define FLT_POS (3.402823466e38f)
#define PTS 32
#define QT 64                    // queries per block
#define CT 64                    // candidates per tile

// -------- scratch (__device__ globals) --------
__device__ __align__(16) float g_xt[Bn * Nn * Cn];   // fp32 (edge gather)
__device__ __align__(16) float g_ah[Bn * Nn * Cn];   // tf32 hi (fp32 bits)
__device__ __align__(16) float g_al[Bn * Nn * Cn];   // tf32 lo (fp32 bits)
__device__ __align__(16) float g_xn[Bn * Nn];        // 0.5*|x|^2
__device__ __align__(16) int   g_idx[Bn * Nn * Kn];
__device__ __align__(16) float g_w1[Cn * On];
__device__ __align__(16) float g_wd[Cn * On];
__device__ float g_scale[On];
__device__ float g_bias[On];

// ---------------- PTX helpers ----------------
__device__ __forceinline__ uint32_t smem_u32(const void* p) {
    uint32_t a;
    asm("{ .reg .u64 t; cvta.to.shared.u64 t, %1; cvt.u32.u64 %0, t; }" : "=r"(a) : "l"(p));
    return a;
}
__device__ __forceinline__ uint32_t f2tf(float x) {
    uint32_t r; asm("cvt.rna.tf32.f32 %0, %1;" : "=r"(r) : "f"(x)); return r;
}
__device__ __forceinline__ void mma_tf32(float* d, const uint32_t* a, const uint32_t* b) {
    asm volatile("mma.sync.aligned.m16n8k8.row.col.f32.tf32.tf32.f32 "
        "{%0,%1,%2,%3}, {%4,%5,%6,%7}, {%8,%9}, {%0,%1,%2,%3};"
        : "+f"(d[0]), "+f"(d[1]), "+f"(d[2]), "+f"(d[3])
        : "r"(a[0]), "r"(a[1]), "r"(a[2]), "r"(a[3]), "r"(b[0]), "r"(b[1]));
}
#define CP_ASYNC16(dst, src) \
    asm volatile("cp.async.cg.shared.global [%0], [%1], 16;" :: "r"(dst), "l"(src))
#define CP_COMMIT() asm volatile("cp.async.commit_group;" ::: "memory")
#define CP_WAIT1()  asm volatile("cp.async.wait_group 1;" ::: "memory")

__device__ __forceinline__ void fma2(unsigned long long& d, unsigned long long a, unsigned long long b) {
    asm("fma.rn.f32x2 %0, %1, %2, %0;" : "+l"(d) : "l"(a), "l"(b));
}
__device__ __forceinline__ unsigned long long pack2(float v) {
    unsigned long long r; asm("mov.b64 %0, {%1, %1};" : "=l"(r) : "f"(v)); return r;
}
__device__ __forceinline__ void unpack2(unsigned long long v, float& lo, float& hi) {
    asm("mov.b64 {%0, %1}, %2;" : "=f"(lo), "=f"(hi) : "l"(v));
}

// ---------------- weight / BN prep ----------------
__global__ void prep_kernel(const float* __restrict__ W,
                            const float* __restrict__ gamma,
                            const float* __restrict__ beta,
                            const float* __restrict__ bn_mean,
                            const float* __restrict__ bn_var) {
    int o = threadIdx.x;
    float sc = gamma[o] * rsqrtf(bn_var[o] + EPSf);
    g_scale[o] = sc;
    g_bias[o]  = beta[o] - bn_mean[o] * sc;
    for (int c = 0; c < Cn; c++) {
        float w1 = W[o * (2 * Cn) + c];
        float w2 = W[o * (2 * Cn) + Cn + c];
        g_w1[c * On + o] = w1;
        g_wd[c * On + o] = w2 - w1;
    }
}

// ---------------- transpose + tf32 hi/lo precompute ----------------
__global__ void transpose_kernel(const float* __restrict__ x) {
    __shared__ float s[32][65];
    int b  = blockIdx.y;
    int nb = blockIdx.x * 32;
    int tx = threadIdx.x, ty = threadIdx.y;
    const float* xb = x + (size_t)b * Cn * Nn;
#pragma unroll
    for (int i = 0; i < 8; i++) {
        int c = ty * 8 + i;
        s[tx][c] = xb[(size_t)c * Nn + nb + tx];
    }
    __syncthreads();
    int t = ty * 32 + tx;
    int r = t >> 3;
    int c0 = (t & 7) * 8;
    size_t base = ((size_t)b * Nn + nb + r) * Cn + c0;
#pragma unroll
    for (int i = 0; i < 8; i++) {
        float v = s[r][c0 + i];
        g_xt[base + i] = v;
        uint32_t hb = f2tf(v);
        g_ah[base + i] = __uint_as_float(hb);
        g_al[base + i] = __uint_as_float(f2tf(v - __uint_as_float(hb)));
    }
}

// ---------------- half squared norms ----------------
__global__ void norm_kernel(const float* __restrict__ x) {
    int n = blockIdx.x * blockDim.x + threadIdx.x;
    int b = blockIdx.y;
    const float* xb = x + (size_t)b * Cn * Nn + n;
    float s = 0.f;
#pragma unroll
    for (int c = 0; c < Cn; c++) { float v = xb[(size_t)c * Nn]; s += v * v; }
    g_xn[b * Nn + n] = 0.5f * s;
}

// ---------------- KNN: tf32 3-pass mma.sync, zero in-loop cvt ----------
// smem floats: AS[h,l][64][68] | BS[2buf][h,l][64][68] | NS[4][64] | S[64][33]
#define ROWF 68
#define AS_COMP (QT * ROWF)                 // 4352 floats
#define AS_OFF 0
#define BS_OFF (2 * AS_COMP)                // 8704
#define BS_COMP (CT * ROWF)                 // 4352
#define BS_BUF (2 * BS_COMP)                // 8704 (hi+lo)
#define NS_OFF (BS_OFF + 2 * BS_BUF)        // 26112
#define S_OFF  (NS_OFF + 4 * CT)            // 26368
#define KNN_SMEM_FLOATS (S_OFF + QT * 33)   // 28480 floats = 113,920 B

__device__ __forceinline__ void prefetch_tile(uint32_t bs_u32, uint32_t ns_u32,
                                              const float* __restrict__ ah,
                                              const float* __restrict__ al,
                                              const float* __restrict__ xn,
                                              int rowbase, int tid) {
#pragma unroll
    for (int i = 0; i < 8; i++) {
        int idx = tid + i * 256;                 // 0..2047
        int comp = idx >> 10;                    // 0=hi 1=lo
        int rem = idx & 1023;                    // 64 rows x 16 f4
        int r = rem >> 4, k4 = rem & 15;
        const float* src = (comp ? al : ah) + (size_t)(rowbase + r) * Cn + k4 * 4;
        CP_ASYNC16(bs_u32 + (uint32_t)(comp * (BS_COMP * 4) + r * (ROWF * 4) + k4 * 16), src);
    }
    if (tid < 16)
        CP_ASYNC16(ns_u32 + (uint32_t)tid * 16, xn + rowbase + tid * 4);
}

__global__ __launch_bounds__(256, 2) void knn_kernel() {
    extern __shared__ __align__(16) float sh[];
    float* NS = sh + NS_OFF;
    float* S  = sh + S_OFF;
    const uint32_t as_u = smem_u32(sh);
    const uint32_t bs_u = smem_u32(sh + BS_OFF);
    const uint32_t ns_u = smem_u32(NS);

    const int tid = threadIdx.x;
    const int wid = tid >> 5, lane = tid & 31;
    const int g = lane >> 2, t4 = lane & 3;
    const int warp_m = wid >> 2;         // 0..1 -> rows m0..m0+31
    const int warp_n = wid & 3;          // 0..3 -> cols n0..n0+15
    const int m0 = warp_m * 32, n0 = warp_n * 16;

    const int b = blockIdx.x >> 8;               // 256 blocks per batch
    const int qbase = (blockIdx.x & 255) << 6;
    const float* ah = g_ah + (size_t)b * Nn * Cn;
    const float* al = g_al + (size_t)b * Nn * Cn;
    const float* xn = g_xn + (size_t)b * Nn;

    // load A hi/lo (2048 f4) + candidate tiles 0,1
#pragma unroll
    for (int i = 0; i < 8; i++) {
        int idx = tid + i * 256;
        int comp = idx >> 10;
        int rem = idx & 1023;
        int r = rem >> 4, k4 = rem & 15;
        const float* src = (comp ? al : ah) + (size_t)(qbase + r) * Cn + k4 * 4;
        CP_ASYNC16(as_u + (uint32_t)(comp * (AS_COMP * 4) + r * (ROWF * 4) + k4 * 16), src);
    }
    prefetch_tile(bs_u, ns_u, ah, al, xn, 0, tid);
    CP_COMMIT();
    prefetch_tile(bs_u + BS_BUF * 4, ns_u + CT * 4, ah, al, xn, CT, tid);
    CP_COMMIT();

    // selection state: 4 threads per query, 8 cols per phase each
    float vtop[Kn]; int itop[Kn];
#pragma unroll
    for (int u = 0; u < Kn; u++) { vtop[u] = FLT_NEG; itop[u] = 0; }
    float vmin = FLT_NEG; int smin = 0;
    const int selq = tid & 63;
    const int selh = tid >> 6;                   // 0..3
    const int qi = qbase + selq;
    const float* Srow = S + selq * 33 + selh * 8;

    // A fragment row bases (floats) within each comp
    const int rA0 = (m0 + g) * ROWF;
    const int rA1 = (m0 + g + 8) * ROWF;
    const int rA2 = (m0 + 16 + g) * ROWF;
    const int rA3 = (m0 + 24 + g) * ROWF;
    const float* ASh = sh;                // hi comp
    const float* ASl = sh + AS_COMP;      // lo comp

#pragma unroll 1
    for (int t = 0; t < Nn / CT; t++) {
        CP_WAIT1();
        __syncthreads();

        const float* Bh = sh + BS_OFF + (t & 1) * BS_BUF;
        const float* Bl = Bh + BS_COMP;
        const float* nsb = NS + (t & 3) * CT;

        float acc[2][2][4];
#pragma unroll
        for (int mt = 0; mt < 2; mt++)
#pragma unroll
            for (int nt = 0; nt < 2; nt++)
#pragma unroll
                for (int r = 0; r < 4; r++) acc[mt][nt][r] = 0.f;

#pragma unroll
        for (int k8 = 0; k8 < 8; k8++) {
            const int kc = k8 * 8 + t4;
            uint32_t ahf[2][4], alf[2][4];
            ahf[0][0] = __float_as_uint(ASh[rA0 + kc]);
            ahf[0][1] = __float_as_uint(ASh[rA1 + kc]);
            ahf[0][2] = __float_as_uint(ASh[rA0 + kc + 4]);
            ahf[0][3] = __float_as_uint(ASh[rA1 + kc + 4]);
            ahf[1][0] = __float_as_uint(ASh[rA2 + kc]);
            ahf[1][1] = __float_as_uint(ASh[rA3 + kc]);
            ahf[1][2] = __float_as_uint(ASh[rA2 + kc + 4]);
            ahf[1][3] = __float_as_uint(ASh[rA3 + kc + 4]);
            alf[0][0] = __float_as_uint(ASl[rA0 + kc]);
            alf[0][1] = __float_as_uint(ASl[rA1 + kc]);
            alf[0][2] = __float_as_uint(ASl[rA0 + kc + 4]);
            alf[0][3] = __float_as_uint(ASl[rA1 + kc + 4]);
            alf[1][0] = __float_as_uint(ASl[rA2 + kc]);
            alf[1][1] = __float_as_uint(ASl[rA3 + kc]);
            alf[1][2] = __float_as_uint(ASl[rA2 + kc + 4]);
            alf[1][3] = __float_as_uint(ASl[rA3 + kc + 4]);
#pragma unroll
            for (int nt = 0; nt < 2; nt++) {
                const int rB = (n0 + nt * 8 + g) * ROWF + k8 * 8 + t4;
                uint32_t bh[2], bl[2];
                bh[0] = __float_as_uint(Bh[rB]);
                bh[1] = __float_as_uint(Bh[rB + 4]);
                bl[0] = __float_as_uint(Bl[rB]);
                bl[1] = __float_as_uint(Bl[rB + 4]);
#pragma unroll
                for (int mt = 0; mt < 2; mt++) {
                    mma_tf32(acc[mt][nt], ahf[mt], bh);
                    mma_tf32(acc[mt][nt], alf[mt], bh);
                    mma_tf32(acc[mt][nt], ahf[mt], bl);
                }
            }
        }

        // two phases of 32 cols; phase p spilled by warps with warp_n>>1 == p
#pragma unroll
        for (int p = 0; p < 2; p++) {
            if ((warp_n >> 1) == p) {
#pragma unroll
                for (int nt = 0; nt < 2; nt++) {
                    int cg = n0 + nt * 8 + 2 * t4;     // global col 0..63
                    int lc = cg - p * 32;              // local col 0..31
                    float nv0 = nsb[cg], nv1 = nsb[cg + 1];
#pragma unroll
                    for (int mt = 0; mt < 2; mt++) {
                        int r0 = m0 + mt * 16 + g;
                        S[r0 * 33 + lc]           = acc[mt][nt][0] - nv0;
                        S[r0 * 33 + lc + 1]       = acc[mt][nt][1] - nv1;
                        S[(r0 + 8) * 33 + lc]     = acc[mt][nt][2] - nv0;
                        S[(r0 + 8) * 33 + lc + 1] = acc[mt][nt][3] - nv1;
                    }
                }
            }
            __syncthreads();
            if (p == 0) {
                if (t + 2 < Nn / CT)
                    prefetch_tile(bs_u + (uint32_t)(t & 1) * (BS_BUF * 4),
                                  ns_u + (uint32_t)((t + 2) & 3) * (CT * 4),
                                  ah, al, xn, (t + 2) * CT, tid);
                CP_COMMIT();
            }
            // selection: 4 threads/query, 8 cols each
            const int jg0 = t * CT + p * 32 + selh * 8;
#pragma unroll
            for (int c = 0; c < 8; c++) {
                float sv = Srow[c];
                if (sv > vmin) {
                    int jg = jg0 + c;
                    if (jg != qi) {
                        vtop[smin] = sv; itop[smin] = jg;
                        float m = vtop[0]; int sm = 0;
#pragma unroll
                        for (int u = 1; u < Kn; u++)
                            if (vtop[u] < m) { m = vtop[u]; sm = u; }
                        vmin = m; smin = sm;
                    }
                }
            }
            __syncthreads();
        }
    }

    // merge 4 partial top-k per query (dump in dead BS region)
    float* mv = sh + BS_OFF;
    int*   mi = (int*)(sh + BS_OFF + 3 * QT * Kn);
    if (selh > 0) {
        int base = ((selh - 1) * QT + selq) * Kn;
#pragma unroll
        for (int u = 0; u < Kn; u++) { mv[base + u] = vtop[u]; mi[base + u] = itop[u]; }
    }
    __syncthreads();
    if (selh == 0) {
        for (int hh = 0; hh < 3; hh++) {
            int base = (hh * QT + selq) * Kn;
#pragma unroll
            for (int u = 0; u < Kn; u++) {
                float sv = mv[base + u];
                if (sv > vmin) {
                    vtop[smin] = sv; itop[smin] = mi[base + u];
                    float m = vtop[0]; int sm = 0;
#pragma unroll
                    for (int w = 1; w < Kn; w++)
                        if (vtop[w] < m) { m = vtop[w]; sm = w; }
                    vmin = m; smin = sm;
                }
            }
        }
        int* op = g_idx + ((size_t)b * Nn + qi) * Kn;
#pragma unroll
        for (int u = 0; u < Kn; u++) op[u] = itop[u];
    }
}

// ---------------- edge conv + BN + lrelu + max over k ----------------
#define EDGE_SMEM_FLOATS (Cn*On + 8*17*Cn + PTS*132 + 2*On)

__global__ __launch_bounds__(256, 2) void edge_kernel(float* __restrict__ out) {
    extern __shared__ float sm[];
    float* w1   = sm;
    float* feat = w1 + Cn * On;
    float* outs = feat + 8 * 17 * Cn;
    float* ssc  = outs + PTS * 132;
    float* sbi  = ssc + On;

    int tid = threadIdx.x, wid = tid >> 5, lane = tid & 31;

    for (int i = tid; i < Cn * On; i += 256) w1[i] = g_w1[i];
    if (tid < On) { ssc[tid] = g_scale[tid]; sbi[tid] = g_bias[tid]; }
    __syncthreads();

    int gp    = blockIdx.x * PTS;
    int b     = gp / Nn;
    int nbase = gp % Nn;
    const float* xtb = g_xt + (size_t)b * Nn * Cn;
    float* fw = feat + wid * 17 * Cn;
    int o0 = lane << 2;

#pragma unroll 1
    for (int pp = 0; pp < PTS / 8; pp++) {
        int pt = pp * 8 + wid;
        int n  = nbase + pt;

        const int* ip = g_idx + ((size_t)b * Nn + n) * Kn;
        int myid = (lane < Kn) ? ip[lane] : n;
#pragma unroll
        for (int r = 0; r < 18; r += 2) {
            int rr = r + (lane >> 4);
            int rowid = __shfl_sync(0xffffffffu, myid, rr & 31);
            if (rr >= Kn) rowid = n;
            if (rr < 17)
                ((float4*)(fw + rr * Cn))[lane & 15] =
                    ((const float4*)(xtb + (size_t)rowid * Cn))[lane & 15];
        }
        __syncwarp();

        float csv[4] = {0.f, 0.f, 0.f, 0.f};
        {
            const float* cen = fw + 16 * Cn;
#pragma unroll
            for (int c = 0; c < Cn; c++) {
                float e = cen[c];
                float4 wv = *(const float4*)(g_wd + c * On + o0);
                csv[0] += wv.x * e; csv[1] += wv.y * e;
                csv[2] += wv.z * e; csv[3] += wv.w * e;
            }
        }

        float mx[4] = {FLT_NEG, FLT_NEG, FLT_NEG, FLT_NEG};
        float mn[4] = {FLT_POS, FLT_POS, FLT_POS, FLT_POS};

#pragma unroll 1
        for (int k0 = 0; k0 < Kn; k0 += 4) {
            unsigned long long acc2[4][2];
#pragma unroll
            for (int j = 0; j < 4; j++) { acc2[j][0] = 0ull; acc2[j][1] = 0ull; }
            const float4* f0 = (const float4*)(fw + (k0 + 0) * Cn);
            const float4* f1 = (const float4*)(fw + (k0 + 1) * Cn);
            const float4* f2 = (const float4*)(fw + (k0 + 2) * Cn);
            const float4* f3 = (const float4*)(fw + (k0 + 3) * Cn);
#pragma unroll
            for (int c4 = 0; c4 < Cn / 4; c4++) {
                float4 e0 = f0[c4], e1 = f1[c4], e2 = f2[c4], e3 = f3[c4];
#pragma unroll
                for (int cc = 0; cc < 4; cc++) {
                    const float* wb = w1 + (c4 * 4 + cc) * On + o0;
                    unsigned long long wA = *(const unsigned long long*)wb;
                    unsigned long long wB = *(const unsigned long long*)(wb + 2);
                    float v0 = (cc == 0) ? e0.x : (cc == 1) ? e0.y : (cc == 2) ? e0.z : e0.w;
                    float v1 = (cc == 0) ? e1.x : (cc == 1) ? e1.y : (cc == 2) ? e1.z : e1.w;
                    float v2 = (cc == 0) ? e2.x : (cc == 1) ? e2.y : (cc == 2) ? e2.z : e2.w;
                    float v3 = (cc == 0) ? e3.x : (cc == 1) ? e3.y : (cc == 2) ? e3.z : e3.w;
                    unsigned long long p0 = pack2(v0), p1 = pack2(v1),
                                       p2 = pack2(v2), p3 = pack2(v3);
                    fma2(acc2[0][0], p0, wA); fma2(acc2[0][1], p0, wB);
                    fma2(acc2[1][0], p1, wA); fma2(acc2[1][1], p1, wB);
                    fma2(acc2[2][0], p2, wA); fma2(acc2[2][1], p2, wB);
                    fma2(acc2[3][0], p3, wA); fma2(acc2[3][1], p3, wB);
                }
            }
#pragma unroll
            for (int j = 0; j < 4; j++) {
                float a0, a1, a2, a3;
                unpack2(acc2[j][0], a0, a1);
                unpack2(acc2[j][1], a2, a3);
                mx[0] = fmaxf(mx[0], a0); mn[0] = fminf(mn[0], a0);
                mx[1] = fmaxf(mx[1], a1); mn[1] = fminf(mn[1], a1);
                mx[2] = fmaxf(mx[2], a2); mn[2] = fminf(mn[2], a2);
                mx[3] = fmaxf(mx[3], a3); mn[3] = fminf(mn[3], a3);
            }
        }

        float* od = outs + pt * 132 + o0;
#pragma unroll
        for (int r = 0; r < 4; r++) {
            float sc = ssc[o0 + r];
            float bi = sbi[o0 + r];
            float base = (sc > 0.f ? mx[r] : mn[r]) + csv[r];
            float yv = fmaf(sc, base, bi);
            yv = yv > 0.f ? yv : NEGf * yv;
            od[r] = yv;
        }
        __syncwarp();
    }

    __syncthreads();
    {
        int o = tid >> 1, h = tid & 1;
        float* dst = out + ((size_t)(b * On + o)) * Nn + nbase + h * 16;
#pragma unroll
        for (int i4 = 0; i4 < 4; i4++) {
            float4 vv;
            vv.x = outs[(h * 16 + i4 * 4 + 0) * 132 + o];
            vv.y = outs[(h * 16 + i4 * 4 + 1) * 132 + o];
            vv.z = outs[(h * 16 + i4 * 4 + 2) * 132 + o];
            vv.w = outs[(h * 16 + i4 * 4 + 3) * 132 + o];
            *(float4*)(dst + i4 * 4) = vv;
        }
    }
}

// ---------------- launch ----------------
extern "C" void kernel_launch(void* const* d_in, const int* in_sizes, int n_in,
                              void* d_out, int out_size) {
    const float* x       = (const float*)d_in[0];
    const float* W       = (const float*)d_in[1];
    const float* gamma   = (const float*)d_in[2];
    const float* beta    = (const float*)d_in[3];
    const float* bn_mean = (const float*)d_in[4];
    const float* bn_var  = (const float*)d_in[5];
    float* out = (float*)d_out;

    const size_t knn_smem  = KNN_SMEM_FLOATS * sizeof(float);
    const size_t edge_smem = EDGE_SMEM_FLOATS * sizeof(float);
    cudaFuncSetAttribute(knn_kernel, cudaFuncAttributeMaxDynamicSharedMemorySize,
                         (int)knn_smem);
    cudaFuncSetAttribute(edge_kernel, cudaFuncAttributeMaxDynamicSharedMemorySize,
                         (int)edge_smem);

    prep_kernel<<<1, On>>>(W, gamma, beta, bn_mean, bn_var);
    transpose_kernel<<<dim3(Nn / 32, Bn), dim3(32, 8)>>>(x);
    norm_kernel<<<dim3(Nn / 256, Bn), 256>>>(x);
    knn_kernel<<<Bn * (Nn / QT), 256, knn_smem>>>();
    edge_kernel<<<(Bn * Nn) / PTS, 256, edge_smem>>>(out);
}

// round 13
// speedup vs baseline: 1.0141x; 1.0141x over previous
#include <cuda_runtime.h>
#include <cstdint>

#define Bn 4
#define Cn 64
#define Nn 16384
#define On 128
#define Kn 16
#define EPSf 1e-5f
#define NEGf 0.2f
#define FLT_NEG (-3.402823466e38f)
#define FLT_POS (3.402823466e38f)
#define PTS 32
#define QT 128
#define CT 128

// -------- scratch (__device__ globals) --------
__device__ __align__(16) float g_xt[Bn * Nn * Cn];   // fp32 (edge gather)
__device__ __align__(16) float g_ah[Bn * Nn * Cn];   // tf32 hi (fp32 bits)
__device__ __align__(16) float g_al[Bn * Nn * Cn];   // tf32 lo (fp32 bits)
__device__ __align__(16) float g_xn[Bn * Nn];        // 0.5*|x|^2
__device__ __align__(16) int   g_idx[Bn * Nn * Kn];
__device__ __align__(16) float g_w1[Cn * On];
__device__ __align__(16) float g_wd[Cn * On];
__device__ float g_scale[On];
__device__ float g_bias[On];

// ---------------- PTX helpers ----------------
__device__ __forceinline__ uint32_t smem_u32(const void* p) {
    uint32_t a;
    asm("{ .reg .u64 t; cvta.to.shared.u64 t, %1; cvt.u32.u64 %0, t; }" : "=r"(a) : "l"(p));
    return a;
}
__device__ __forceinline__ uint32_t f2tf(float x) {
    uint32_t r; asm("cvt.rna.tf32.f32 %0, %1;" : "=r"(r) : "f"(x)); return r;
}
__device__ __forceinline__ void mma_tf32(float* d, const uint32_t* a, const uint32_t* b) {
    asm volatile("mma.sync.aligned.m16n8k8.row.col.f32.tf32.tf32.f32 "
        "{%0,%1,%2,%3}, {%4,%5,%6,%7}, {%8,%9}, {%0,%1,%2,%3};"
        : "+f"(d[0]), "+f"(d[1]), "+f"(d[2]), "+f"(d[3])
        : "r"(a[0]), "r"(a[1]), "r"(a[2]), "r"(a[3]), "r"(b[0]), "r"(b[1]));
}
#define CP_ASYNC16(dst, src) \
    asm volatile("cp.async.cg.shared.global [%0], [%1], 16;" :: "r"(dst), "l"(src))
#define CP_COMMIT() asm volatile("cp.async.commit_group;" ::: "memory")
#define CP_WAIT1()  asm volatile("cp.async.wait_group 1;" ::: "memory")

__device__ __forceinline__ void fma2(unsigned long long& d, unsigned long long a, unsigned long long b) {
    asm("fma.rn.f32x2 %0, %1, %2, %0;" : "+l"(d) : "l"(a), "l"(b));
}
__device__ __forceinline__ unsigned long long pack2(float v) {
    unsigned long long r; asm("mov.b64 %0, {%1, %1};" : "=l"(r) : "f"(v)); return r;
}
__device__ __forceinline__ void unpack2(unsigned long long v, float& lo, float& hi) {
    asm("mov.b64 {%0, %1}, %2;" : "=f"(lo), "=f"(hi) : "l"(v));
}

// ---------------- weight / BN prep ----------------
__global__ void prep_kernel(const float* __restrict__ W,
                            const float* __restrict__ gamma,
                            const float* __restrict__ beta,
                            const float* __restrict__ bn_mean,
                            const float* __restrict__ bn_var) {
    int o = threadIdx.x;
    float sc = gamma[o] * rsqrtf(bn_var[o] + EPSf);
    g_scale[o] = sc;
    g_bias[o]  = beta[o] - bn_mean[o] * sc;
    for (int c = 0; c < Cn; c++) {
        float w1 = W[o * (2 * Cn) + c];
        float w2 = W[o * (2 * Cn) + Cn + c];
        g_w1[c * On + o] = w1;
        g_wd[c * On + o] = w2 - w1;
    }
}

// ---------------- transpose + tf32 hi/lo precompute ----------------
__global__ void transpose_kernel(const float* __restrict__ x) {
    __shared__ float s[32][65];
    int b  = blockIdx.y;
    int nb = blockIdx.x * 32;
    int tx = threadIdx.x, ty = threadIdx.y;
    const float* xb = x + (size_t)b * Cn * Nn;
#pragma unroll
    for (int i = 0; i < 8; i++) {
        int c = ty * 8 + i;
        s[tx][c] = xb[(size_t)c * Nn + nb + tx];
    }
    __syncthreads();
    int t = ty * 32 + tx;
    int r = t >> 3;
    int c0 = (t & 7) * 8;
    size_t base = ((size_t)b * Nn + nb + r) * Cn + c0;
#pragma unroll
    for (int i = 0; i < 8; i++) {
        float v = s[r][c0 + i];
        g_xt[base + i] = v;
        uint32_t hb = f2tf(v);
        g_ah[base + i] = __uint_as_float(hb);
        g_al[base + i] = __uint_as_float(f2tf(v - __uint_as_float(hb)));
    }
}

// ---------------- half squared norms ----------------
__global__ void norm_kernel(const float* __restrict__ x) {
    int n = blockIdx.x * blockDim.x + threadIdx.x;
    int b = blockIdx.y;
    const float* xb = x + (size_t)b * Cn * Nn + n;
    float s = 0.f;
#pragma unroll
    for (int c = 0; c < Cn; c++) { float v = xb[(size_t)c * Nn]; s += v * v; }
    g_xn[b * Nn + n] = 0.5f * s;
}

// ---------------- KNN: tf32 3-pass, 512 threads, big tiles ------------
// floats: AS[h,l][128][68] | BS[2buf fp32][128][68] | NS[4][128] | S[128][129]
#define ROWF 68
#define AS_COMP (QT * ROWF)                  // 8704
#define BS_OFF  (2 * AS_COMP)                // 17408
#define BS_BUF  (CT * ROWF)                  // 8704
#define NS_OFF  (BS_OFF + 2 * BS_BUF)        // 34816
#define S_OFF   (NS_OFF + 4 * CT)            // 35328
#define SSTR 129
#define KNN_SMEM_FLOATS (S_OFF + QT * SSTR)  // 51840 floats = 207,360 B

__device__ __forceinline__ void prefetch_tile(uint32_t bs_u32, uint32_t ns_u32,
                                              const float* __restrict__ xt,
                                              const float* __restrict__ xn,
                                              int rowbase, int tid) {
#pragma unroll
    for (int i = 0; i < 4; i++) {
        int idx = tid + i * 512;                 // 0..2047 (128 rows x 16 f4)
        int r = idx >> 4, k4 = idx & 15;
        CP_ASYNC16(bs_u32 + (uint32_t)(r * (ROWF * 4) + k4 * 16),
                   xt + (size_t)(rowbase + r) * Cn + k4 * 4);
    }
    if (tid < 32)
        CP_ASYNC16(ns_u32 + (uint32_t)tid * 16, xn + rowbase + tid * 4);
}

__global__ __launch_bounds__(512, 1) void knn_kernel() {
    extern __shared__ __align__(16) float sh[];
    float* ASh = sh;                     // hi comp
    float* ASl = sh + AS_COMP;           // lo comp
    float* NS  = sh + NS_OFF;
    float* S   = sh + S_OFF;
    const uint32_t as_u = smem_u32(sh);
    const uint32_t bs_u = smem_u32(sh + BS_OFF);
    const uint32_t ns_u = smem_u32(NS);

    const int tid = threadIdx.x;
    const int wid = tid >> 5, lane = tid & 31;
    const int g = lane >> 2, t4 = lane & 3;
    const int warp_m = wid >> 2;         // 0..3 -> 32 rows each
    const int warp_n = wid & 3;          // 0..3 -> 32 cols each
    const int m0 = warp_m * 32, n0 = warp_n * 32;

    const int b = blockIdx.x >> 7;               // 128 blocks per batch
    const int qbase = (blockIdx.x & 127) << 7;
    const float* ah = g_ah + (size_t)b * Nn * Cn;
    const float* al = g_al + (size_t)b * Nn * Cn;
    const float* xt = g_xt + (size_t)b * Nn * Cn;   // fp32 B source
    const float* xn = g_xn + (size_t)b * Nn;

    // load A hi/lo (4096 f4) in the same group as tile 0
#pragma unroll
    for (int i = 0; i < 8; i++) {
        int idx = tid + i * 512;
        int comp = idx >> 11;
        int rem = idx & 2047;
        int r = rem >> 4, k4 = rem & 15;
        const float* src = (comp ? al : ah) + (size_t)(qbase + r) * Cn + k4 * 4;
        CP_ASYNC16(as_u + (uint32_t)(comp * (AS_COMP * 4) + r * (ROWF * 4) + k4 * 16), src);
    }
    prefetch_tile(bs_u, ns_u, xt, xn, 0, tid);
    CP_COMMIT();
    prefetch_tile(bs_u + BS_BUF * 4, ns_u + CT * 4, xt, xn, CT, tid);
    CP_COMMIT();

    // selection state: 4 threads per query, 32 cols each
    float vtop[Kn]; int itop[Kn];
#pragma unroll
    for (int u = 0; u < Kn; u++) { vtop[u] = FLT_NEG; itop[u] = 0; }
    float vmin = FLT_NEG; int smin = 0;
    const int selq = tid & 127;
    const int selh = tid >> 7;                 // 0..3
    const int qi = qbase + selq;
    const float* Srow = S + selq * SSTR + selh * 32;

    // A fragment row bases
    const int rA0 = (m0 + g) * ROWF;
    const int rA1 = (m0 + g + 8) * ROWF;
    const int rA2 = (m0 + 16 + g) * ROWF;
    const int rA3 = (m0 + 24 + g) * ROWF;

#pragma unroll 1
    for (int t = 0; t < Nn / CT; t++) {
        CP_WAIT1();
        __syncthreads();

        const float* Bbuf = sh + BS_OFF + (t & 1) * BS_BUF;
        const float* nsb  = NS + (t & 3) * CT;

        float acc[2][4][4];
#pragma unroll
        for (int mt = 0; mt < 2; mt++)
#pragma unroll
            for (int nt = 0; nt < 4; nt++)
#pragma unroll
                for (int r = 0; r < 4; r++) acc[mt][nt][r] = 0.f;

#pragma unroll
        for (int k8 = 0; k8 < 8; k8++) {
            const int kc = k8 * 8 + t4;
            uint32_t ahf[2][4], alf[2][4];
            ahf[0][0] = __float_as_uint(ASh[rA0 + kc]);
            ahf[0][1] = __float_as_uint(ASh[rA1 + kc]);
            ahf[0][2] = __float_as_uint(ASh[rA0 + kc + 4]);
            ahf[0][3] = __float_as_uint(ASh[rA1 + kc + 4]);
            ahf[1][0] = __float_as_uint(ASh[rA2 + kc]);
            ahf[1][1] = __float_as_uint(ASh[rA3 + kc]);
            ahf[1][2] = __float_as_uint(ASh[rA2 + kc + 4]);
            ahf[1][3] = __float_as_uint(ASh[rA3 + kc + 4]);
            alf[0][0] = __float_as_uint(ASl[rA0 + kc]);
            alf[0][1] = __float_as_uint(ASl[rA1 + kc]);
            alf[0][2] = __float_as_uint(ASl[rA0 + kc + 4]);
            alf[0][3] = __float_as_uint(ASl[rA1 + kc + 4]);
            alf[1][0] = __float_as_uint(ASl[rA2 + kc]);
            alf[1][1] = __float_as_uint(ASl[rA3 + kc]);
            alf[1][2] = __float_as_uint(ASl[rA2 + kc + 4]);
            alf[1][3] = __float_as_uint(ASl[rA3 + kc + 4]);
#pragma unroll
            for (int nt = 0; nt < 4; nt++) {
                const int rB = (n0 + nt * 8 + g) * ROWF + kc;
                float b0 = Bbuf[rB], b1 = Bbuf[rB + 4];
                uint32_t bh[2], bl[2];
                bh[0] = f2tf(b0); bl[0] = f2tf(b0 - __uint_as_float(bh[0]));
                bh[1] = f2tf(b1); bl[1] = f2tf(b1 - __uint_as_float(bh[1]));
#pragma unroll
                for (int mt = 0; mt < 2; mt++) {
                    mma_tf32(acc[mt][nt], ahf[mt], bh);
                    mma_tf32(acc[mt][nt], alf[mt], bh);
                    mma_tf32(acc[mt][nt], ahf[mt], bl);
                }
            }
        }

        // spill all 128 cols (every warp owns a distinct 32x32 region)
#pragma unroll
        for (int nt = 0; nt < 4; nt++) {
            int c0 = n0 + nt * 8 + 2 * t4;
            float nv0 = nsb[c0], nv1 = nsb[c0 + 1];
#pragma unroll
            for (int mt = 0; mt < 2; mt++) {
                int r0 = m0 + mt * 16 + g;
                S[r0 * SSTR + c0]           = acc[mt][nt][0] - nv0;
                S[r0 * SSTR + c0 + 1]       = acc[mt][nt][1] - nv1;
                S[(r0 + 8) * SSTR + c0]     = acc[mt][nt][2] - nv0;
                S[(r0 + 8) * SSTR + c0 + 1] = acc[mt][nt][3] - nv1;
            }
        }
        __syncthreads();

        if (t + 2 < Nn / CT)
            prefetch_tile(bs_u + (uint32_t)(t & 1) * (BS_BUF * 4),
                          ns_u + (uint32_t)((t + 2) & 3) * (CT * 4),
                          xt, xn, (t + 2) * CT, tid);
        CP_COMMIT();

        // selection: 4 threads per query, 32 cols each
        const int jg0 = t * CT + selh * 32;
#pragma unroll 4
        for (int c = 0; c < 32; c++) {
            float sv = Srow[c];
            if (sv > vmin) {
                int jg = jg0 + c;
                if (jg != qi) {
                    vtop[smin] = sv; itop[smin] = jg;
                    float m = vtop[0]; int sm = 0;
#pragma unroll
                    for (int u = 1; u < Kn; u++)
                        if (vtop[u] < m) { m = vtop[u]; sm = u; }
                    vmin = m; smin = sm;
                }
            }
        }
    }

    // merge 4 partial top-k per query (dump in dead BS region)
    __syncthreads();
    float* mv = sh + BS_OFF;
    int*   mi = (int*)(sh + BS_OFF + 3 * QT * Kn);
    if (selh > 0) {
        int base = ((selh - 1) * QT + selq) * Kn;
#pragma unroll
        for (int u = 0; u < Kn; u++) { mv[base + u] = vtop[u]; mi[base + u] = itop[u]; }
    }
    __syncthreads();
    if (selh == 0) {
        for (int hh = 0; hh < 3; hh++) {
            int base = (hh * QT + selq) * Kn;
#pragma unroll
            for (int u = 0; u < Kn; u++) {
                float sv = mv[base + u];
                if (sv > vmin) {
                    vtop[smin] = sv; itop[smin] = mi[base + u];
                    float m = vtop[0]; int sm = 0;
#pragma unroll
                    for (int w = 1; w < Kn; w++)
                        if (vtop[w] < m) { m = vtop[w]; sm = w; }
                    vmin = m; smin = sm;
                }
            }
        }
        int* op = g_idx + ((size_t)b * Nn + qi) * Kn;
#pragma unroll
        for (int u = 0; u < Kn; u++) op[u] = itop[u];
    }
}

// ---------------- edge conv + BN + lrelu + max over k ----------------
#define EDGE_SMEM_FLOATS (Cn*On + 8*17*Cn + PTS*132 + 2*On)

__global__ __launch_bounds__(256, 2) void edge_kernel(float* __restrict__ out) {
    extern __shared__ float sm[];
    float* w1   = sm;
    float* feat = w1 + Cn * On;
    float* outs = feat + 8 * 17 * Cn;
    float* ssc  = outs + PTS * 132;
    float* sbi  = ssc + On;

    int tid = threadIdx.x, wid = tid >> 5, lane = tid & 31;

    for (int i = tid; i < Cn * On; i += 256) w1[i] = g_w1[i];
    if (tid < On) { ssc[tid] = g_scale[tid]; sbi[tid] = g_bias[tid]; }
    __syncthreads();

    int gp    = blockIdx.x * PTS;
    int b     = gp / Nn;
    int nbase = gp % Nn;
    const float* xtb = g_xt + (size_t)b * Nn * Cn;
    float* fw = feat + wid * 17 * Cn;
    int o0 = lane << 2;

#pragma unroll 1
    for (int pp = 0; pp < PTS / 8; pp++) {
        int pt = pp * 8 + wid;
        int n  = nbase + pt;

        const int* ip = g_idx + ((size_t)b * Nn + n) * Kn;
        int myid = (lane < Kn) ? ip[lane] : n;
#pragma unroll
        for (int r = 0; r < 18; r += 2) {
            int rr = r + (lane >> 4);
            int rowid = __shfl_sync(0xffffffffu, myid, rr & 31);
            if (rr >= Kn) rowid = n;
            if (rr < 17)
                ((float4*)(fw + rr * Cn))[lane & 15] =
                    ((const float4*)(xtb + (size_t)rowid * Cn))[lane & 15];
        }
        __syncwarp();

        float csv[4] = {0.f, 0.f, 0.f, 0.f};
        {
            const float* cen = fw + 16 * Cn;
#pragma unroll
            for (int c = 0; c < Cn; c++) {
                float e = cen[c];
                float4 wv = *(const float4*)(g_wd + c * On + o0);
                csv[0] += wv.x * e; csv[1] += wv.y * e;
                csv[2] += wv.z * e; csv[3] += wv.w * e;
            }
        }

        float mx[4] = {FLT_NEG, FLT_NEG, FLT_NEG, FLT_NEG};
        float mn[4] = {FLT_POS, FLT_POS, FLT_POS, FLT_POS};

#pragma unroll 1
        for (int k0 = 0; k0 < Kn; k0 += 4) {
            unsigned long long acc2[4][2];
#pragma unroll
            for (int j = 0; j < 4; j++) { acc2[j][0] = 0ull; acc2[j][1] = 0ull; }
            const float4* f0 = (const float4*)(fw + (k0 + 0) * Cn);
            const float4* f1 = (const float4*)(fw + (k0 + 1) * Cn);
            const float4* f2 = (const float4*)(fw + (k0 + 2) * Cn);
            const float4* f3 = (const float4*)(fw + (k0 + 3) * Cn);
#pragma unroll
            for (int c4 = 0; c4 < Cn / 4; c4++) {
                float4 e0 = f0[c4], e1 = f1[c4], e2 = f2[c4], e3 = f3[c4];
#pragma unroll
                for (int cc = 0; cc < 4; cc++) {
                    const float* wb = w1 + (c4 * 4 + cc) * On + o0;
                    unsigned long long wA = *(const unsigned long long*)wb;
                    unsigned long long wB = *(const unsigned long long*)(wb + 2);
                    float v0 = (cc == 0) ? e0.x : (cc == 1) ? e0.y : (cc == 2) ? e0.z : e0.w;
                    float v1 = (cc == 0) ? e1.x : (cc == 1) ? e1.y : (cc == 2) ? e1.z : e1.w;
                    float v2 = (cc == 0) ? e2.x : (cc == 1) ? e2.y : (cc == 2) ? e2.z : e2.w;
                    float v3 = (cc == 0) ? e3.x : (cc == 1) ? e3.y : (cc == 2) ? e3.z : e3.w;
                    unsigned long long p0 = pack2(v0), p1 = pack2(v1),
                                       p2 = pack2(v2), p3 = pack2(v3);
                    fma2(acc2[0][0], p0, wA); fma2(acc2[0][1], p0, wB);
                    fma2(acc2[1][0], p1, wA); fma2(acc2[1][1], p1, wB);
                    fma2(acc2[2][0], p2, wA); fma2(acc2[2][1], p2, wB);
                    fma2(acc2[3][0], p3, wA); fma2(acc2[3][1], p3, wB);
                }
            }
#pragma unroll
            for (int j = 0; j < 4; j++) {
                float a0, a1, a2, a3;
                unpack2(acc2[j][0], a0, a1);
                unpack2(acc2[j][1], a2, a3);
                mx[0] = fmaxf(mx[0], a0); mn[0] = fminf(mn[0], a0);
                mx[1] = fmaxf(mx[1], a1); mn[1] = fminf(mn[1], a1);
                mx[2] = fmaxf(mx[2], a2); mn[2] = fminf(mn[2], a2);
                mx[3] = fmaxf(mx[3], a3); mn[3] = fminf(mn[3], a3);
            }
        }

        float* od = outs + pt * 132 + o0;
#pragma unroll
        for (int r = 0; r < 4; r++) {
            float sc = ssc[o0 + r];
            float bi = sbi[o0 + r];
            float base = (sc > 0.f ? mx[r] : mn[r]) + csv[r];
            float yv = fmaf(sc, base, bi);
            yv = yv > 0.f ? yv : NEGf * yv;
            od[r] = yv;
        }
        __syncwarp();
    }

    __syncthreads();
    {
        int o = tid >> 1, h = tid & 1;
        float* dst = out + ((size_t)(b * On + o)) * Nn + nbase + h * 16;
#pragma unroll
        for (int i4 = 0; i4 < 4; i4++) {
            float4 vv;
            vv.x = outs[(h * 16 + i4 * 4 + 0) * 132 + o];
            vv.y = outs[(h * 16 + i4 * 4 + 1) * 132 + o];
            vv.z = outs[(h * 16 + i4 * 4 + 2) * 132 + o];
            vv.w = outs[(h * 16 + i4 * 4 + 3) * 132 + o];
            *(float4*)(dst + i4 * 4) = vv;
        }
    }
}

// ---------------- launch ----------------
extern "C" void kernel_launch(void* const* d_in, const int* in_sizes, int n_in,
                              void* d_out, int out_size) {
    const float* x       = (const float*)d_in[0];
    const float* W       = (const float*)d_in[1];
    const float* gamma   = (const float*)d_in[2];
    const float* beta    = (const float*)d_in[3];
    const float* bn_mean = (const float*)d_in[4];
    const float* bn_var  = (const float*)d_in[5];
    float* out = (float*)d_out;

    const size_t knn_smem  = KNN_SMEM_FLOATS * sizeof(float);
    const size_t edge_smem = EDGE_SMEM_FLOATS * sizeof(float);
    cudaFuncSetAttribute(knn_kernel, cudaFuncAttributeMaxDynamicSharedMemorySize,
                         (int)knn_smem);
    cudaFuncSetAttribute(edge_kernel, cudaFuncAttributeMaxDynamicSharedMemorySize,
                         (int)edge_smem);

    prep_kernel<<<1, On>>>(W, gamma, beta, bn_mean, bn_var);
    transpose_kernel<<<dim3(Nn / 32, Bn), dim3(32, 8)>>>(x);
    norm_kernel<<<dim3(Nn / 256, Bn), 256>>>(x);
    knn_kernel<<<Bn * (Nn / QT), 512, knn_smem>>>();
    edge_kernel<<<(Bn * Nn) / PTS, 256, edge_smem>>>(out);
}

// round 14
// speedup vs baseline: 1.1673x; 1.1510x over previous
#include <cuda_runtime.h>
#include <cstdint>

#define Bn 4
#define Cn 64
#define Nn 16384
#define On 128
#define Kn 16
#define EPSf 1e-5f
#define NEGf 0.2f
#define FLT_NEG (-3.402823466e38f)
#define FLT_POS (3.402823466e38f)
#define PTS 32
#define QT 128
#define CT 32

// -------- scratch (__device__ globals) --------
__device__ __align__(16) float g_xt[Bn * Nn * Cn];       // fp32 (edge gather)
__device__ __align__(16) float g_ai[Bn * Nn * 2 * Cn];   // interleaved (hi,lo) tf32 pairs
__device__ __align__(16) float g_xn[Bn * Nn];            // 0.5*|x|^2
__device__ __align__(16) int   g_idx[Bn * Nn * Kn];
__device__ __align__(16) float g_w1[Cn * On];
__device__ __align__(16) float g_wd[Cn * On];
__device__ float g_scale[On];
__device__ float g_bias[On];

// ---------------- PTX helpers ----------------
__device__ __forceinline__ uint32_t smem_u32(const void* p) {
    uint32_t a;
    asm("{ .reg .u64 t; cvta.to.shared.u64 t, %1; cvt.u32.u64 %0, t; }" : "=r"(a) : "l"(p));
    return a;
}
__device__ __forceinline__ uint32_t f2tf(float x) {
    uint32_t r; asm("cvt.rna.tf32.f32 %0, %1;" : "=r"(r) : "f"(x)); return r;
}
__device__ __forceinline__ void mma_tf32(float* d, const uint32_t* a, const uint32_t* b) {
    asm volatile("mma.sync.aligned.m16n8k8.row.col.f32.tf32.tf32.f32 "
        "{%0,%1,%2,%3}, {%4,%5,%6,%7}, {%8,%9}, {%0,%1,%2,%3};"
        : "+f"(d[0]), "+f"(d[1]), "+f"(d[2]), "+f"(d[3])
        : "r"(a[0]), "r"(a[1]), "r"(a[2]), "r"(a[3]), "r"(b[0]), "r"(b[1]));
}
#define CP_ASYNC16(dst, src) \
    asm volatile("cp.async.cg.shared.global [%0], [%1], 16;" :: "r"(dst), "l"(src))
#define CP_COMMIT() asm volatile("cp.async.commit_group;" ::: "memory")
#define CP_WAIT1()  asm volatile("cp.async.wait_group 1;" ::: "memory")

__device__ __forceinline__ void fma2(unsigned long long& d, unsigned long long a, unsigned long long b) {
    asm("fma.rn.f32x2 %0, %1, %2, %0;" : "+l"(d) : "l"(a), "l"(b));
}
__device__ __forceinline__ unsigned long long pack2(float v) {
    unsigned long long r; asm("mov.b64 %0, {%1, %1};" : "=l"(r) : "f"(v)); return r;
}
__device__ __forceinline__ void unpack2(unsigned long long v, float& lo, float& hi) {
    asm("mov.b64 {%0, %1}, %2;" : "=f"(lo), "=f"(hi) : "l"(v));
}

// ---------------- weight / BN prep ----------------
__global__ void prep_kernel(const float* __restrict__ W,
                            const float* __restrict__ gamma,
                            const float* __restrict__ beta,
                            const float* __restrict__ bn_mean,
                            const float* __restrict__ bn_var) {
    int o = threadIdx.x;
    float sc = gamma[o] * rsqrtf(bn_var[o] + EPSf);
    g_scale[o] = sc;
    g_bias[o]  = beta[o] - bn_mean[o] * sc;
    for (int c = 0; c < Cn; c++) {
        float w1 = W[o * (2 * Cn) + c];
        float w2 = W[o * (2 * Cn) + Cn + c];
        g_w1[c * On + o] = w1;
        g_wd[c * On + o] = w2 - w1;
    }
}

// ---------------- transpose + interleaved tf32 hi/lo ----------------
__global__ void transpose_kernel(const float* __restrict__ x) {
    __shared__ float s[32][65];
    int b  = blockIdx.y;
    int nb = blockIdx.x * 32;
    int tx = threadIdx.x, ty = threadIdx.y;
    const float* xb = x + (size_t)b * Cn * Nn;
#pragma unroll
    for (int i = 0; i < 8; i++) {
        int c = ty * 8 + i;
        s[tx][c] = xb[(size_t)c * Nn + nb + tx];
    }
    __syncthreads();
    int t = ty * 32 + tx;
    int r = t >> 3;
    int c0 = (t & 7) * 8;
    size_t base  = ((size_t)b * Nn + nb + r) * Cn + c0;
    size_t base2 = ((size_t)b * Nn + nb + r) * (2 * Cn) + 2 * c0;
#pragma unroll
    for (int i = 0; i < 8; i++) {
        float v = s[r][c0 + i];
        g_xt[base + i] = v;
        uint32_t hb = f2tf(v);
        float hv = __uint_as_float(hb);
        g_ai[base2 + 2 * i]     = hv;
        g_ai[base2 + 2 * i + 1] = __uint_as_float(f2tf(v - hv));
    }
}

// ---------------- half squared norms ----------------
__global__ void norm_kernel(const float* __restrict__ x) {
    int n = blockIdx.x * blockDim.x + threadIdx.x;
    int b = blockIdx.y;
    const float* xb = x + (size_t)b * Cn * Nn + n;
    float s = 0.f;
#pragma unroll
    for (int c = 0; c < Cn; c++) { float v = xb[(size_t)c * Nn]; s += v * v; }
    g_xn[b * Nn + n] = 0.5f * s;
}

// ---------------- KNN: tf32 3-pass, zero in-loop cvt, paired hi/lo ----
// floats: AS[128][136] | BS[2][32][136] | NS[2][32] | STG[8][32*9]
#define ROW2 136
#define AS_FL (QT * ROW2)                   // 17408
#define BS_OFF AS_FL
#define BS_BUF (CT * ROW2)                  // 4352
#define NS_OFF (BS_OFF + 2 * BS_BUF)        // 26112
#define STG_OFF (NS_OFF + 2 * CT)           // 26176
#define KNN_SMEM_FLOATS (STG_OFF + 8 * 288) // 28480 fl = 113,920 B

__device__ __forceinline__ void prefetch_tile(uint32_t bs_u32, uint32_t ns_u32,
                                              const float* __restrict__ ai,
                                              const float* __restrict__ xn,
                                              int rowbase, int tid) {
#pragma unroll
    for (int i = 0; i < 4; i++) {
        int idx = tid + i * 256;                 // 0..1023 (32 rows x 32 chunks)
        int r = idx >> 5, c = idx & 31;
        CP_ASYNC16(bs_u32 + (uint32_t)(r * (ROW2 * 4) + c * 16),
                   ai + (size_t)(rowbase + r) * (2 * Cn) + c * 4);
    }
    if (tid < 8)
        CP_ASYNC16(ns_u32 + (uint32_t)tid * 16, xn + rowbase + tid * 4);
}

__global__ __launch_bounds__(256, 2) void knn_kernel() {
    extern __shared__ __align__(16) float sh[];
    const float* ASp = sh;
    float* NS  = sh + NS_OFF;
    const uint32_t as_u = smem_u32(sh);
    const uint32_t bs_u = smem_u32(sh + BS_OFF);
    const uint32_t ns_u = smem_u32(NS);

    const int tid = threadIdx.x;
    const int wid = tid >> 5, lane = tid & 31;
    const int g = lane >> 2, t4 = lane & 3;
    const int warp_m = wid >> 1;           // 0..3 -> 32 query rows
    const int warp_n = wid & 1;            // 0..1 -> 16 cand cols
    const int m0 = warp_m * 32;

    const int b = blockIdx.x >> 7;
    const int qbase = (blockIdx.x & 127) << 7;
    const float* ai = g_ai + (size_t)b * Nn * (2 * Cn);
    const float* xn = g_xn + (size_t)b * Nn;

    // load A (128 rows x 32 chunks) + tiles 0,1
#pragma unroll
    for (int i = 0; i < 16; i++) {
        int idx = tid + i * 256;
        int r = idx >> 5, c = idx & 31;
        CP_ASYNC16(as_u + (uint32_t)(r * (ROW2 * 4) + c * 16),
                   ai + (size_t)(qbase + r) * (2 * Cn) + c * 4);
    }
    prefetch_tile(bs_u, ns_u, ai, xn, 0, tid);
    CP_COMMIT();
    prefetch_tile(bs_u + BS_BUF * 4, ns_u + CT * 4, ai, xn, CT, tid);
    CP_COMMIT();

    // selection state: one query per thread (per warp_n half)
    float vtop[Kn]; int itop[Kn];
#pragma unroll
    for (int u = 0; u < Kn; u++) { vtop[u] = FLT_NEG; itop[u] = 0; }
    float vmin = FLT_NEG; int smin = 0;
    const int myrow = 16 * (t4 >> 1) + 8 * (t4 & 1) + g;   // 0..31
    const int qi = qbase + m0 + myrow;
    float* stg = sh + STG_OFF + wid * 288;

#pragma unroll 1
    for (int t = 0; t < Nn / CT; t++) {
        CP_WAIT1();
        __syncthreads();

        const float* Bbuf = sh + BS_OFF + (t & 1) * BS_BUF;
        const float* nsb  = NS + (t & 1) * CT;

        float acc[2][2][4];
#pragma unroll
        for (int mt = 0; mt < 2; mt++)
#pragma unroll
            for (int nt = 0; nt < 2; nt++)
#pragma unroll
                for (int r = 0; r < 4; r++) acc[mt][nt][r] = 0.f;

#pragma unroll
        for (int k8 = 0; k8 < 8; k8++) {
            const int kk2 = 2 * (8 * k8 + t4);
            uint32_t ah[2][4], al[2][4];
#pragma unroll
            for (int mt = 0; mt < 2; mt++) {
                const float* rb = ASp + (m0 + 16 * mt + g) * ROW2;
                float2 v0 = *(const float2*)(rb + kk2);
                float2 v1 = *(const float2*)(rb + 8 * ROW2 + kk2);
                float2 v2 = *(const float2*)(rb + kk2 + 8);
                float2 v3 = *(const float2*)(rb + 8 * ROW2 + kk2 + 8);
                ah[mt][0] = __float_as_uint(v0.x); al[mt][0] = __float_as_uint(v0.y);
                ah[mt][1] = __float_as_uint(v1.x); al[mt][1] = __float_as_uint(v1.y);
                ah[mt][2] = __float_as_uint(v2.x); al[mt][2] = __float_as_uint(v2.y);
                ah[mt][3] = __float_as_uint(v3.x); al[mt][3] = __float_as_uint(v3.y);
            }
#pragma unroll
            for (int nt = 0; nt < 2; nt++) {
                const float* rbB = Bbuf + (warp_n * 16 + nt * 8 + g) * ROW2;
                float2 w0 = *(const float2*)(rbB + kk2);
                float2 w1 = *(const float2*)(rbB + kk2 + 8);
                uint32_t bh[2] = { __float_as_uint(w0.x), __float_as_uint(w1.x) };
                uint32_t bl[2] = { __float_as_uint(w0.y), __float_as_uint(w1.y) };
#pragma unroll
                for (int mt = 0; mt < 2; mt++) {
                    mma_tf32(acc[mt][nt], ah[mt], bh);
                    mma_tf32(acc[mt][nt], al[mt], bh);
                    mma_tf32(acc[mt][nt], ah[mt], bl);
                }
            }
        }

        // two 8-col phases per warp: private spill + select (syncwarp only)
#pragma unroll
        for (int ph = 0; ph < 2; ph++) {
            float nv0 = nsb[warp_n * 16 + ph * 8 + 2 * t4];
            float nv1 = nsb[warp_n * 16 + ph * 8 + 2 * t4 + 1];
#pragma unroll
            for (int mt = 0; mt < 2; mt++) {
                int rl = 16 * mt + g;
                stg[rl * 9 + 2 * t4]           = acc[mt][ph][0] - nv0;
                stg[rl * 9 + 2 * t4 + 1]       = acc[mt][ph][1] - nv1;
                stg[(rl + 8) * 9 + 2 * t4]     = acc[mt][ph][2] - nv0;
                stg[(rl + 8) * 9 + 2 * t4 + 1] = acc[mt][ph][3] - nv1;
            }
            __syncwarp();
            const int jg0 = t * CT + warp_n * 16 + ph * 8;
            const float* srow = stg + myrow * 9;
#pragma unroll
            for (int c = 0; c < 8; c++) {
                float sv = srow[c];
                if (sv > vmin) {
                    int jg = jg0 + c;
                    if (jg != qi) {
                        vtop[smin] = sv; itop[smin] = jg;
                        float m = vtop[0]; int sm = 0;
#pragma unroll
                        for (int u = 1; u < Kn; u++)
                            if (vtop[u] < m) { m = vtop[u]; sm = u; }
                        vmin = m; smin = sm;
                    }
                }
            }
            __syncwarp();
        }
        __syncthreads();

        if (t + 2 < Nn / CT)
            prefetch_tile(bs_u + (uint32_t)(t & 1) * (BS_BUF * 4),
                          ns_u + (uint32_t)(t & 1) * (CT * 4),
                          ai, xn, (t + 2) * CT, tid);
        CP_COMMIT();
    }

    // merge the two warp_n partials per query (reuse BS region)
    __syncthreads();
    float* mv = sh + BS_OFF;
    int*   mi = (int*)(sh + BS_OFF + 2048);
    const int qslot = m0 + myrow;               // 0..127
    if (warp_n == 1) {
#pragma unroll
        for (int u = 0; u < Kn; u++) {
            mv[qslot * Kn + u] = vtop[u];
            mi[qslot * Kn + u] = itop[u];
        }
    }
    __syncthreads();
    if (warp_n == 0) {
#pragma unroll
        for (int u = 0; u < Kn; u++) {
            float sv = mv[qslot * Kn + u];
            if (sv > vmin) {
                vtop[smin] = sv; itop[smin] = mi[qslot * Kn + u];
                float m = vtop[0]; int sm = 0;
#pragma unroll
                for (int w = 1; w < Kn; w++)
                    if (vtop[w] < m) { m = vtop[w]; sm = w; }
                vmin = m; smin = sm;
            }
        }
        int* op = g_idx + ((size_t)b * Nn + qi) * Kn;
#pragma unroll
        for (int u = 0; u < Kn; u++) op[u] = itop[u];
    }
}

// ---------------- edge conv + BN + lrelu + max over k ----------------
#define EDGE_SMEM_FLOATS (Cn*On + 8*17*Cn + PTS*132 + 2*On)

__global__ __launch_bounds__(256, 2) void edge_kernel(float* __restrict__ out) {
    extern __shared__ float sm[];
    float* w1   = sm;
    float* feat = w1 + Cn * On;
    float* outs = feat + 8 * 17 * Cn;
    float* ssc  = outs + PTS * 132;
    float* sbi  = ssc + On;

    int tid = threadIdx.x, wid = tid >> 5, lane = tid & 31;

    for (int i = tid; i < Cn * On; i += 256) w1[i] = g_w1[i];
    if (tid < On) { ssc[tid] = g_scale[tid]; sbi[tid] = g_bias[tid]; }
    __syncthreads();

    int gp    = blockIdx.x * PTS;
    int b     = gp / Nn;
    int nbase = gp % Nn;
    const float* xtb = g_xt + (size_t)b * Nn * Cn;
    float* fw = feat + wid * 17 * Cn;
    int o0 = lane << 2;

#pragma unroll 1
    for (int pp = 0; pp < PTS / 8; pp++) {
        int pt = pp * 8 + wid;
        int n  = nbase + pt;

        const int* ip = g_idx + ((size_t)b * Nn + n) * Kn;
        int myid = (lane < Kn) ? ip[lane] : n;
#pragma unroll
        for (int r = 0; r < 18; r += 2) {
            int rr = r + (lane >> 4);
            int rowid = __shfl_sync(0xffffffffu, myid, rr & 31);
            if (rr >= Kn) rowid = n;
            if (rr < 17)
                ((float4*)(fw + rr * Cn))[lane & 15] =
                    ((const float4*)(xtb + (size_t)rowid * Cn))[lane & 15];
        }
        __syncwarp();

        float csv[4] = {0.f, 0.f, 0.f, 0.f};
        {
            const float* cen = fw + 16 * Cn;
#pragma unroll
            for (int c = 0; c < Cn; c++) {
                float e = cen[c];
                float4 wv = *(const float4*)(g_wd + c * On + o0);
                csv[0] += wv.x * e; csv[1] += wv.y * e;
                csv[2] += wv.z * e; csv[3] += wv.w * e;
            }
        }

        float mx[4] = {FLT_NEG, FLT_NEG, FLT_NEG, FLT_NEG};
        float mn[4] = {FLT_POS, FLT_POS, FLT_POS, FLT_POS};

#pragma unroll 1
        for (int k0 = 0; k0 < Kn; k0 += 4) {
            unsigned long long acc2[4][2];
#pragma unroll
            for (int j = 0; j < 4; j++) { acc2[j][0] = 0ull; acc2[j][1] = 0ull; }
            const float4* f0 = (const float4*)(fw + (k0 + 0) * Cn);
            const float4* f1 = (const float4*)(fw + (k0 + 1) * Cn);
            const float4* f2 = (const float4*)(fw + (k0 + 2) * Cn);
            const float4* f3 = (const float4*)(fw + (k0 + 3) * Cn);
#pragma unroll
            for (int c4 = 0; c4 < Cn / 4; c4++) {
                float4 e0 = f0[c4], e1 = f1[c4], e2 = f2[c4], e3 = f3[c4];
#pragma unroll
                for (int cc = 0; cc < 4; cc++) {
                    const float* wb = w1 + (c4 * 4 + cc) * On + o0;
                    unsigned long long wA = *(const unsigned long long*)wb;
                    unsigned long long wB = *(const unsigned long long*)(wb + 2);
                    float v0 = (cc == 0) ? e0.x : (cc == 1) ? e0.y : (cc == 2) ? e0.z : e0.w;
                    float v1 = (cc == 0) ? e1.x : (cc == 1) ? e1.y : (cc == 2) ? e1.z : e1.w;
                    float v2 = (cc == 0) ? e2.x : (cc == 1) ? e2.y : (cc == 2) ? e2.z : e2.w;
                    float v3 = (cc == 0) ? e3.x : (cc == 1) ? e3.y : (cc == 2) ? e3.z : e3.w;
                    unsigned long long p0 = pack2(v0), p1 = pack2(v1),
                                       p2 = pack2(v2), p3 = pack2(v3);
                    fma2(acc2[0][0], p0, wA); fma2(acc2[0][1], p0, wB);
                    fma2(acc2[1][0], p1, wA); fma2(acc2[1][1], p1, wB);
                    fma2(acc2[2][0], p2, wA); fma2(acc2[2][1], p2, wB);
                    fma2(acc2[3][0], p3, wA); fma2(acc2[3][1], p3, wB);
                }
            }
#pragma unroll
            for (int j = 0; j < 4; j++) {
                float a0, a1, a2, a3;
                unpack2(acc2[j][0], a0, a1);
                unpack2(acc2[j][1], a2, a3);
                mx[0] = fmaxf(mx[0], a0); mn[0] = fminf(mn[0], a0);
                mx[1] = fmaxf(mx[1], a1); mn[1] = fminf(mn[1], a1);
                mx[2] = fmaxf(mx[2], a2); mn[2] = fminf(mn[2], a2);
                mx[3] = fmaxf(mx[3], a3); mn[3] = fminf(mn[3], a3);
            }
        }

        float* od = outs + pt * 132 + o0;
#pragma unroll
        for (int r = 0; r < 4; r++) {
            float sc = ssc[o0 + r];
            float bi = sbi[o0 + r];
            float base = (sc > 0.f ? mx[r] : mn[r]) + csv[r];
            float yv = fmaf(sc, base, bi);
            yv = yv > 0.f ? yv : NEGf * yv;
            od[r] = yv;
        }
        __syncwarp();
    }

    __syncthreads();
    {
        int o = tid >> 1, h = tid & 1;
        float* dst = out + ((size_t)(b * On + o)) * Nn + nbase + h * 16;
#pragma unroll
        for (int i4 = 0; i4 < 4; i4++) {
            float4 vv;
            vv.x = outs[(h * 16 + i4 * 4 + 0) * 132 + o];
            vv.y = outs[(h * 16 + i4 * 4 + 1) * 132 + o];
            vv.z = outs[(h * 16 + i4 * 4 + 2) * 132 + o];
            vv.w = outs[(h * 16 + i4 * 4 + 3) * 132 + o];
            *(float4*)(dst + i4 * 4) = vv;
        }
    }
}

// ---------------- launch ----------------
extern "C" void kernel_launch(void* const* d_in, const int* in_sizes, int n_in,
                              void* d_out, int out_size) {
    const float* x       = (const float*)d_in[0];
    const float* W       = (const float*)d_in[1];
    const float* gamma   = (const float*)d_in[2];
    const float* beta    = (const float*)d_in[3];
    const float* bn_mean = (const float*)d_in[4];
    const float* bn_var  = (const float*)d_in[5];
    float* out = (float*)d_out;

    const size_t knn_smem  = KNN_SMEM_FLOATS * sizeof(float);
    const size_t edge_smem = EDGE_SMEM_FLOATS * sizeof(float);
    cudaFuncSetAttribute(knn_kernel, cudaFuncAttributeMaxDynamicSharedMemorySize,
                         (int)knn_smem);
    cudaFuncSetAttribute(edge_kernel, cudaFuncAttributeMaxDynamicSharedMemorySize,
                         (int)edge_smem);

    prep_kernel<<<1, On>>>(W, gamma, beta, bn_mean, bn_var);
    transpose_kernel<<<dim3(Nn / 32, Bn), dim3(32, 8)>>>(x);
    norm_kernel<<<dim3(Nn / 256, Bn), 256>>>(x);
    knn_kernel<<<Bn * (Nn / QT), 256, knn_smem>>>();
    edge_kernel<<<(Bn * Nn) / PTS, 256, edge_smem>>>(out);
}